// round 11
// baseline (speedup 1.0000x reference)
#include <cuda_runtime.h>
#include <cfloat>

// Reverse cummax along axis 1 of [B=16, H=128, W=128, C=256] fp32.
// One thread per (b, w, c4) float4-column; walk h backward with running max.
//
// FINAL — converged optimum, reproduced 3x (78.2 / 78.9 / 78.5 us kernel):
//   - 128-thread CTAs x 1024 blocks: balanced 7 CTAs/SM. (256thr/512CTA had
//     a 4-vs-3 CTA/SM imbalance costing ~5% DRAM BW; 64thr also lost.)
//   - Simple interleaved unroll-4 body: ptxas batches the 4 LDG.E.128 ahead
//     of the FMNMX chain itself. Explicit batching, unroll-8, and 32-bit
//     pointer arithmetic all measured neutral-to-worse.
//   - DEFAULT cache policy: each store dirties the line just loaded;
//     evict-first (__ldcs/__stcs) broke LTS fill/dirty coalescing (-30%).
// 6.2 TB/s (78% of 8 TB/s HBM spec) = the measured ceiling for 1:1
// read/write streaming on this part. Hard HBM-bound: issue 5%, fma 0.3%.

static constexpr int B = 16;
static constexpr int H = 128;
static constexpr int W = 128;
static constexpr int C = 256;
static constexpr int C4 = C / 4;            // 64 float4 per row
static constexpr int STRIDE_H = W * C4;     // 8192 float4 between h slices
static constexpr int COLS = B * W * C4;     // 131072 columns
static constexpr int PER_B = W * C4;        // 8192 columns per batch
static constexpr long PER_B_ELEMS = (long)H * W * C4;

__global__ void __launch_bounds__(128) rev_cummax_kernel(
    const float4* __restrict__ in, float4* __restrict__ out)
{
    int col = blockIdx.x * blockDim.x + threadIdx.x;

    int b   = col >> 13;            // col / 8192
    int rem = col & (PER_B - 1);
    long base = (long)b * PER_B_ELEMS + rem;

    float4 m = make_float4(-FLT_MAX, -FLT_MAX, -FLT_MAX, -FLT_MAX);

    #pragma unroll 4
    for (int h = H - 1; h >= 0; --h) {
        long idx = base + (long)h * STRIDE_H;
        float4 v = in[idx];
        m.x = fmaxf(m.x, v.x);
        m.y = fmaxf(m.y, v.y);
        m.z = fmaxf(m.z, v.z);
        m.w = fmaxf(m.w, v.w);
        out[idx] = m;
    }
}

extern "C" void kernel_launch(void* const* d_in, const int* in_sizes, int n_in,
                              void* d_out, int out_size)
{
    (void)in_sizes; (void)n_in; (void)out_size;
    const float4* in  = (const float4*)d_in[0];
    float4*       out = (float4*)d_out;

    const int threads = 128;
    const int blocks  = COLS / threads;  // 1024, exact
    rev_cummax_kernel<<<blocks, threads>>>(in, out);
}

// round 12
// speedup vs baseline: 1.0046x; 1.0046x over previous
#include <cuda_runtime.h>
#include <cfloat>

// Reverse cummax along axis 1 of [B=16, H=128, W=128, C=256] fp32.
// One thread per (b, w, c4) float4-column; walk h backward with running max.
//
// FINAL — converged optimum, reproduced 3x (78.2 / 78.5 / 78.9 us kernel).
// R10's 81.4us on this identical binary was environmental variance (L1/issue
// metrics shifted with unchanged SASS), calibrating the noise floor at ~±3us.
//   - 128-thread CTAs x 1024 blocks: balanced 7 CTAs/SM. (256thr/512CTA had
//     a 4-vs-3 CTA/SM imbalance costing ~5% DRAM BW; 64thr also lost.)
//   - Simple interleaved unroll-4 body: ptxas batches the 4 LDG.E.128 ahead
//     of the FMNMX chain itself. Explicit batching, unroll-8, and 32-bit
//     pointer arithmetic all measured neutral-to-worse.
//   - DEFAULT cache policy: each store dirties the line just loaded;
//     evict-first (__ldcs/__stcs) broke LTS fill/dirty coalescing (-30%).
// 6.2 TB/s (78% of 8 TB/s HBM spec) = the measured ceiling for 1:1
// read/write streaming on this part. Hard HBM-bound: issue 5%, fma 0.3%.

static constexpr int B = 16;
static constexpr int H = 128;
static constexpr int W = 128;
static constexpr int C = 256;
static constexpr int C4 = C / 4;            // 64 float4 per row
static constexpr int STRIDE_H = W * C4;     // 8192 float4 between h slices
static constexpr int COLS = B * W * C4;     // 131072 columns
static constexpr int PER_B = W * C4;        // 8192 columns per batch
static constexpr long PER_B_ELEMS = (long)H * W * C4;

__global__ void __launch_bounds__(128) rev_cummax_kernel(
    const float4* __restrict__ in, float4* __restrict__ out)
{
    int col = blockIdx.x * blockDim.x + threadIdx.x;

    int b   = col >> 13;            // col / 8192
    int rem = col & (PER_B - 1);
    long base = (long)b * PER_B_ELEMS + rem;

    float4 m = make_float4(-FLT_MAX, -FLT_MAX, -FLT_MAX, -FLT_MAX);

    #pragma unroll 4
    for (int h = H - 1; h >= 0; --h) {
        long idx = base + (long)h * STRIDE_H;
        float4 v = in[idx];
        m.x = fmaxf(m.x, v.x);
        m.y = fmaxf(m.y, v.y);
        m.z = fmaxf(m.z, v.z);
        m.w = fmaxf(m.w, v.w);
        out[idx] = m;
    }
}

extern "C" void kernel_launch(void* const* d_in, const int* in_sizes, int n_in,
                              void* d_out, int out_size)
{
    (void)in_sizes; (void)n_in; (void)out_size;
    const float4* in  = (const float4*)d_in[0];
    float4*       out = (float4*)d_out;

    const int threads = 128;
    const int blocks  = COLS / threads;  // 1024, exact
    rev_cummax_kernel<<<blocks, threads>>>(in, out);
}

// round 14
// speedup vs baseline: 1.0681x; 1.0632x over previous
#include <cuda_runtime.h>
#include <cfloat>

// Reverse cummax along axis 1 of [B=16, H=128, W=128, C=256] fp32.
// R12: thread coarsening — each thread walks TWO float4-columns (2 float4
// apart... actually 32 columns apart within the row, see mapping) with
// independent running maxes. 64-thread CTAs x 1024 blocks keeps the balanced
// ~7 CTAs/SM layout while doubling per-thread MLP (8 LDG.128 in flight) with
// naturally interleaved, unrestructured schedules per chain.

static constexpr int B = 16;
static constexpr int H = 128;
static constexpr int W = 128;
static constexpr int C = 256;
static constexpr int C4 = C / 4;            // 64 float4 per row
static constexpr int STRIDE_H = W * C4;     // 8192 float4 between h slices
static constexpr int COLS = B * W * C4;     // 131072 columns
static constexpr int PER_B = W * C4;        // 8192 columns per batch
static constexpr long PER_B_ELEMS = (long)H * W * C4;

// 64 threads/CTA, 2 columns/thread -> 128 columns/CTA -> 1024 CTAs.
// Thread t in CTA blk handles columns blk*128 + t and blk*128 + 64 + t:
// each warp's 32 lanes touch 32 consecutive float4 (512B) per access.

__global__ void __launch_bounds__(64) rev_cummax_kernel(
    const float4* __restrict__ in, float4* __restrict__ out)
{
    int col0 = blockIdx.x * 128 + threadIdx.x;
    int col1 = col0 + 64;

    int b0   = col0 >> 13;
    int b1   = col1 >> 13;
    long base0 = (long)b0 * PER_B_ELEMS + (col0 & (PER_B - 1));
    long base1 = (long)b1 * PER_B_ELEMS + (col1 & (PER_B - 1));

    float4 m0 = make_float4(-FLT_MAX, -FLT_MAX, -FLT_MAX, -FLT_MAX);
    float4 m1 = m0;

    #pragma unroll 4
    for (int h = H - 1; h >= 0; --h) {
        long off = (long)h * STRIDE_H;
        float4 v0 = in[base0 + off];
        float4 v1 = in[base1 + off];
        m0.x = fmaxf(m0.x, v0.x);
        m0.y = fmaxf(m0.y, v0.y);
        m0.z = fmaxf(m0.z, v0.z);
        m0.w = fmaxf(m0.w, v0.w);
        m1.x = fmaxf(m1.x, v1.x);
        m1.y = fmaxf(m1.y, v1.y);
        m1.z = fmaxf(m1.z, v1.z);
        m1.w = fmaxf(m1.w, v1.w);
        out[base0 + off] = m0;
        out[base1 + off] = m1;
    }
}

extern "C" void kernel_launch(void* const* d_in, const int* in_sizes, int n_in,
                              void* d_out, int out_size)
{
    (void)in_sizes; (void)n_in; (void)out_size;
    const float4* in  = (const float4*)d_in[0];
    float4*       out = (float4*)d_out;

    const int threads = 64;
    const int blocks  = COLS / 128;   // 1024, exact
    rev_cummax_kernel<<<blocks, threads>>>(in, out);
}